// round 4
// baseline (speedup 1.0000x reference)
#include <cuda_runtime.h>
#include <cstdint>

// Problem constants
#define LL   1024   // sequence length
#define DM   768    // d_model
#define NH   12     // heads
#define FD   16     // feature dim per head
#define HD   64     // head dim (v)
#define CH   64     // chunk length
#define NC   16     // number of chunks (LL/CH)
#define DP   288    // padded expanded feature dim (273 -> 288)
#define CHUNK_ELT (DP*HD)   // 18432 floats per (head,chunk) state

// Scratch (static device globals; no allocation)
__device__ float g_Q   [LL * NH * FD];        // (t, h*16+f)
__device__ float g_K   [LL * NH * FD];
__device__ float g_V   [LL * DM];             // (t, h*64+d)
__device__ float g_Qf  [NH * NC * CHUNK_ELT]; // [h][c][n][i]  n=feature, i=token-in-chunk
__device__ float g_Kf  [NH * NC * CHUNK_ELT];
__device__ float g_S   [NH * NC * CHUNK_ELT]; // per-chunk KV sums -> exclusive prefix
__device__ float g_ksum[NH * NC * DP];        // per-chunk k-feature sums -> exclusive prefix
__device__ float g_Y   [LL * DM];             // attention output before Wo

// ---------------------------------------------------------------------------
// TF32 helpers
// ---------------------------------------------------------------------------
__device__ __forceinline__ uint32_t f2tf32(float x) {
    uint32_t r;
    asm volatile("cvt.rna.tf32.f32 %0, %1;" : "=r"(r) : "f"(x));
    return r;
}

__device__ __forceinline__ void mma_tf32(float c[4], const uint32_t a[4], const uint32_t b[2]) {
    asm volatile("mma.sync.aligned.m16n8k8.row.col.f32.tf32.tf32.f32 "
                 "{%0,%1,%2,%3}, {%4,%5,%6,%7}, {%8,%9}, {%0,%1,%2,%3};\n"
                 : "+f"(c[0]), "+f"(c[1]), "+f"(c[2]), "+f"(c[3])
                 : "r"(a[0]), "r"(a[1]), "r"(a[2]), "r"(a[3]),
                   "r"(b[0]), "r"(b[1]));
}

// ---------------------------------------------------------------------------
// 3xTF32 tensor-core GEMM: C[1024 x N] = A[1024 x K] @ B[K x N], row-major.
// Block tile 128x64, 256 threads = 8 warps, each warp a 32x32 tile
// (2 m-subtiles x 4 n-subtiles of m16n8k8). A,B split into tf32 hi+lo;
// C = Ahi*Bhi + Ahi*Blo + Alo*Bhi  (error ~2^-22, effectively fp32-exact).
// smem stride 20 == 4 (mod 32) makes every fragment LDS pattern hit 32
// distinct banks (addr = 20*(lane>>2) + (lane&3) + const).
// ---------------------------------------------------------------------------
__global__ __launch_bounds__(256) void tf32_gemm(const float* __restrict__ A,
                                                 const float* __restrict__ B,
                                                 float* __restrict__ C,
                                                 int N, int K) {
    __shared__ uint32_t Ah[128 * 20], Al[128 * 20];
    __shared__ uint32_t Bh[64 * 20],  Bl[64 * 20];
    const int tid  = threadIdx.x;
    const int lane = tid & 31, w = tid >> 5;
    const int wm = w >> 1, wn = w & 1;          // 4 x 2 warps
    const int gid = lane >> 2, tig = lane & 3;
    const int bm = blockIdx.y * 128, bn = blockIdx.x * 64;

    float acc[2][4][4] = {};                    // [mtile][ntile][reg]

    for (int k0 = 0; k0 < K; k0 += 16) {
        // ---- stage A tile (128 x 16) with hi/lo split ----
#pragma unroll
        for (int it = 0; it < 2; it++) {
            int idx = tid + it * 256;           // float4 index
            int r = idx >> 2, c4 = (idx & 3) * 4;
            float4 v = *(const float4*)&A[(bm + r) * K + k0 + c4];
            float vv[4] = { v.x, v.y, v.z, v.w };
#pragma unroll
            for (int j = 0; j < 4; j++) {
                uint32_t hi = f2tf32(vv[j]);
                Ah[r * 20 + c4 + j] = hi;
                Al[r * 20 + c4 + j] = f2tf32(vv[j] - __uint_as_float(hi));
            }
        }
        // ---- stage B tile (16 x 64) transposed to [n][k] with hi/lo split ----
        {
            int kk = tid >> 4, n4 = (tid & 15) * 4;
            float4 v = *(const float4*)&B[(k0 + kk) * N + bn + n4];
            float vv[4] = { v.x, v.y, v.z, v.w };
#pragma unroll
            for (int j = 0; j < 4; j++) {
                uint32_t hi = f2tf32(vv[j]);
                Bh[(n4 + j) * 20 + kk] = hi;
                Bl[(n4 + j) * 20 + kk] = f2tf32(vv[j] - __uint_as_float(hi));
            }
        }
        __syncthreads();

#pragma unroll
        for (int ks = 0; ks < 2; ks++) {
            const int kb = ks * 8;
            uint32_t ah[2][4], al[2][4], bh[4][2], bl[4][2];
#pragma unroll
            for (int mt = 0; mt < 2; mt++) {
                int rb = wm * 32 + mt * 16;
                ah[mt][0] = Ah[(rb + gid)     * 20 + kb + tig];
                ah[mt][1] = Ah[(rb + gid + 8) * 20 + kb + tig];
                ah[mt][2] = Ah[(rb + gid)     * 20 + kb + tig + 4];
                ah[mt][3] = Ah[(rb + gid + 8) * 20 + kb + tig + 4];
                al[mt][0] = Al[(rb + gid)     * 20 + kb + tig];
                al[mt][1] = Al[(rb + gid + 8) * 20 + kb + tig];
                al[mt][2] = Al[(rb + gid)     * 20 + kb + tig + 4];
                al[mt][3] = Al[(rb + gid + 8) * 20 + kb + tig + 4];
            }
#pragma unroll
            for (int nt = 0; nt < 4; nt++) {
                int nb = wn * 32 + nt * 8;
                bh[nt][0] = Bh[(nb + gid) * 20 + kb + tig];
                bh[nt][1] = Bh[(nb + gid) * 20 + kb + tig + 4];
                bl[nt][0] = Bl[(nb + gid) * 20 + kb + tig];
                bl[nt][1] = Bl[(nb + gid) * 20 + kb + tig + 4];
            }
#pragma unroll
            for (int mt = 0; mt < 2; mt++)
#pragma unroll
                for (int nt = 0; nt < 4; nt++) {
                    mma_tf32(acc[mt][nt], ah[mt], bh[nt]);
                    mma_tf32(acc[mt][nt], ah[mt], bl[nt]);
                    mma_tf32(acc[mt][nt], al[mt], bh[nt]);
                }
        }
        __syncthreads();
    }

    // ---- epilogue ----
#pragma unroll
    for (int mt = 0; mt < 2; mt++)
#pragma unroll
        for (int nt = 0; nt < 4; nt++) {
            int row = bm + wm * 32 + mt * 16 + gid;
            int col = bn + wn * 32 + nt * 8 + tig * 2;
            float2 lo = make_float2(acc[mt][nt][0], acc[mt][nt][1]);
            float2 hi = make_float2(acc[mt][nt][2], acc[mt][nt][3]);
            *(float2*)&C[row * N + col]       = lo;
            *(float2*)&C[(row + 8) * N + col] = hi;
        }
}

// ---------------------------------------------------------------------------
// Featurize: taylor_exp_feature_map (Q and K in one launch, blockIdx.z).
// dst[h][c][n][i]: n=0 -> 1 ; 1..16 -> x/2 ; 17..272 -> x_a*x_b/(4*sqrt2); pad 0
// ---------------------------------------------------------------------------
__global__ __launch_bounds__(256) void featurize_k() {
    const int which = blockIdx.z;
    const float* __restrict__ src = which ? g_K : g_Q;
    float* __restrict__ dst = which ? g_Kf : g_Qf;
    const int c = blockIdx.x, h = blockIdx.y;
    __shared__ float xs[64][17];
    const int tid = threadIdx.x;
    for (int idx = tid; idx < CH * FD; idx += 256) {
        int i = idx >> 4, f = idx & 15;
        xs[i][f] = src[(c * CH + i) * (NH * FD) + h * FD + f];
    }
    __syncthreads();
    float* out = dst + (h * NC + c) * CHUNK_ELT;
    const float S1 = 0.5f;                    // 1/RRD
    const float S2 = 0.17677669529663687f;    // 1/(sqrt(2)*sqrt(16))
    for (int idx = tid; idx < CHUNK_ELT; idx += 256) {
        int n = idx >> 6, i = idx & 63;
        float v;
        if (n == 0)        v = 1.0f;
        else if (n <= 16)  v = xs[i][n - 1] * S1;
        else if (n <= 272) { int p = n - 17; v = xs[i][p >> 4] * xs[i][p & 15] * S2; }
        else               v = 0.0f;
        out[idx] = v;
    }
}

// ---------------------------------------------------------------------------
// Per-chunk KV state: S[h][c][n][d] = sum_i Kf[h][c][n][i] * V[c*64+i][h*64+d]
// Also ksum[h][c][n] = sum_i Kf[n][i].  Grid: (3 n-tiles of 96, NC, NH).
// ---------------------------------------------------------------------------
__global__ __launch_bounds__(256) void chunk_kv_k() {
    const int nt = blockIdx.x, c = blockIdx.y, h = blockIdx.z;
    __shared__ __align__(16) float Ks[96 * 64];
    __shared__ __align__(16) float Vs[64 * 64];
    const int tid = threadIdx.x;
    const float* kf = g_Kf + ((h * NC + c) * DP + nt * 96) * 64;
    for (int idx = tid; idx < 96 * 64 / 4; idx += 256)
        ((float4*)Ks)[idx] = ((const float4*)kf)[idx];
    const float* vp = g_V + (c * CH) * DM + h * HD;
    for (int idx = tid; idx < 64 * 16; idx += 256) {
        int i = idx >> 4, dd = idx & 15;
        ((float4*)Vs)[i * 16 + dd] = ((const float4*)(vp + i * DM))[dd];
    }
    __syncthreads();
    const int ty = tid >> 4, tx = tid & 15;
    const int nb = ty * 6;
    float acc[6][4] = {};
    for (int i = 0; i < 64; i++) {
        float4 v4 = *(const float4*)&Vs[i * 64 + tx * 4];
#pragma unroll
        for (int m = 0; m < 6; m++) {
            float a = Ks[(nb + m) * 64 + i];
            acc[m][0] += a * v4.x; acc[m][1] += a * v4.y;
            acc[m][2] += a * v4.z; acc[m][3] += a * v4.w;
        }
    }
    float* sp = g_S + ((h * NC + c) * DP + nt * 96) * 64;
#pragma unroll
    for (int m = 0; m < 6; m++) {
        float4 o = make_float4(acc[m][0], acc[m][1], acc[m][2], acc[m][3]);
        *(float4*)&sp[(nb + m) * 64 + tx * 4] = o;
    }
    if (tid < 96) {
        float s = 0.f;
        for (int k = 0; k < 64; k++) s += Ks[tid * 64 + ((tid + k) & 63)];  // skewed: no bank conflicts
        g_ksum[(h * NC + c) * DP + nt * 96 + tid] = s;
    }
}

// ---------------------------------------------------------------------------
// Exclusive prefix over chunks (in place), for g_S and g_ksum.
// ---------------------------------------------------------------------------
__global__ __launch_bounds__(256) void prefix_k() {
    const int gid = blockIdx.x * 256 + threadIdx.x;
    const int NS = NH * CHUNK_ELT;  // 221184
    if (gid < NS) {
        int h = gid / CHUNK_ELT, e = gid % CHUNK_ELT;
        float* base = g_S + h * NC * CHUNK_ELT + e;
        float acc = 0.f;
#pragma unroll
        for (int c = 0; c < NC; c++) {
            float v = base[c * CHUNK_ELT];
            base[c * CHUNK_ELT] = acc;
            acc += v;
        }
    } else {
        int j = gid - NS;
        if (j < NH * DP) {
            int h = j / DP, n = j % DP;
            float* base = g_ksum + h * NC * DP + n;
            float acc = 0.f;
#pragma unroll
            for (int c = 0; c < NC; c++) {
                float v = base[c * DP];
                base[c * DP] = acc;
                acc += v;
            }
        }
    }
}

// ---------------------------------------------------------------------------
// Chunk attention: per (chunk, head) block.
//   A[i][j]   = sum_n Qf[n][i]*Kf[n][j]   (masked j<=i)
//   num[i][d] = sum_n Qf[n][i]*Sprev[n][d] + sum_j A[i][j]*V[j][d]
//   den[i]    = sum_n Qf[n][i]*ksumprev[n] + sum_j A[i][j]
//   Y[t][h*64+d] = num/(den+1e-12)
// ---------------------------------------------------------------------------
__global__ __launch_bounds__(256) void chunk_attn_k() {
    const int c = blockIdx.x, h = blockIdx.y;
    extern __shared__ __align__(16) float sm[];
    float* Qs  = sm;                 // [n][i] 288x64
    float* Ks  = sm + CHUNK_ELT;     // [n][j] 288x64
    float* Vs  = sm + 2 * CHUNK_ELT; // [j][d] 64x64
    float* Asm = Vs + 64 * 64;       // [i][j] 64x64
    const int tid = threadIdx.x;

    const float* qf = g_Qf + (h * NC + c) * CHUNK_ELT;
    const float* kf = g_Kf + (h * NC + c) * CHUNK_ELT;
    for (int idx = tid; idx < CHUNK_ELT / 4; idx += 256) {
        ((float4*)Qs)[idx] = ((const float4*)qf)[idx];
        ((float4*)Ks)[idx] = ((const float4*)kf)[idx];
    }
    const float* vp = g_V + (c * CH) * DM + h * HD;
    for (int idx = tid; idx < 64 * 16; idx += 256) {
        int i = idx >> 4, dd = idx & 15;
        ((float4*)Vs)[i * 16 + dd] = ((const float4*)(vp + i * DM))[dd];
    }
    __syncthreads();

    const int ty = tid >> 4, tx = tid & 15;
    const int i0 = ty * 4, c0 = tx * 4;
    const float* Sx = g_S + (h * NC + c) * CHUNK_ELT;
    const float* kx = g_ksum + (h * NC + c) * DP;

    float aA[4][4] = {};   // QK^T scores (i x j)
    float aN[4][4] = {};   // numerator   (i x d)
    float aD[4] = {};      // denominator (i)

#pragma unroll 2
    for (int n = 0; n < DP; n++) {
        float4 q4 = *(const float4*)&Qs[n * 64 + i0];
        float4 k4 = *(const float4*)&Ks[n * 64 + c0];
        float4 s4 = __ldg((const float4*)(Sx + n * 64 + c0));
        float ks  = __ldg(kx + n);
        float q[4] = { q4.x, q4.y, q4.z, q4.w };
        float kk[4] = { k4.x, k4.y, k4.z, k4.w };
        float ss[4] = { s4.x, s4.y, s4.z, s4.w };
#pragma unroll
        for (int m = 0; m < 4; m++) {
#pragma unroll
            for (int j = 0; j < 4; j++) {
                aA[m][j] += q[m] * kk[j];
                aN[m][j] += q[m] * ss[j];
            }
            aD[m] += q[m] * ks;
        }
    }

    // causal mask (j <= i) and stash to smem
#pragma unroll
    for (int m = 0; m < 4; m++) {
        int ig = i0 + m;
        float4 r;
        r.x = (c0 + 0 <= ig) ? aA[m][0] : 0.0f;
        r.y = (c0 + 1 <= ig) ? aA[m][1] : 0.0f;
        r.z = (c0 + 2 <= ig) ? aA[m][2] : 0.0f;
        r.w = (c0 + 3 <= ig) ? aA[m][3] : 0.0f;
        *(float4*)&Asm[ig * 64 + c0] = r;
    }
    __syncthreads();

    // intra-chunk: num += A @ V ; den += rowsum(A)
    for (int j = 0; j < 64; j++) {
        float4 v4 = *(const float4*)&Vs[j * 64 + c0];
#pragma unroll
        for (int m = 0; m < 4; m++) {
            float a = Asm[(i0 + m) * 64 + j];
            aN[m][0] += a * v4.x; aN[m][1] += a * v4.y;
            aN[m][2] += a * v4.z; aN[m][3] += a * v4.w;
            aD[m] += a;
        }
    }

    float* yp = g_Y + (c * CH) * DM + h * HD;
#pragma unroll
    for (int m = 0; m < 4; m++) {
        float inv = 1.0f / (aD[m] + 1e-12f);
        float4 o = make_float4(aN[m][0] * inv, aN[m][1] * inv,
                               aN[m][2] * inv, aN[m][3] * inv);
        *(float4*)&yp[(i0 + m) * DM + c0] = o;
    }
}

// ---------------------------------------------------------------------------
extern "C" void kernel_launch(void* const* d_in, const int* in_sizes, int n_in,
                              void* d_out, int out_size) {
    const float* hs = (const float*)d_in[0];
    const float* Wq = (const float*)d_in[1];
    const float* Wk = (const float*)d_in[2];
    const float* Wv = (const float*)d_in[3];
    const float* Wo = (const float*)d_in[4];
    float* out = (float*)d_out;

    const int attn_smem = (2 * CHUNK_ELT + 2 * 64 * 64) * 4;  // 180224 B
    cudaFuncSetAttribute(chunk_attn_k, cudaFuncAttributeMaxDynamicSharedMemorySize, attn_smem);

    float* dQ; cudaGetSymbolAddress((void**)&dQ, g_Q);
    float* dK; cudaGetSymbolAddress((void**)&dK, g_K);
    float* dV; cudaGetSymbolAddress((void**)&dV, g_V);
    float* dY; cudaGetSymbolAddress((void**)&dY, g_Y);

    dim3 thr(256);
    // projections via 3xTF32 tensor-core GEMM (block tile 128x64)
    tf32_gemm<<<dim3(3, 8),  thr>>>(hs, Wq, dQ, NH * FD, DM);
    tf32_gemm<<<dim3(3, 8),  thr>>>(hs, Wk, dK, NH * FD, DM);
    tf32_gemm<<<dim3(12, 8), thr>>>(hs, Wv, dV, DM, DM);
    featurize_k<<<dim3(NC, NH, 2), thr>>>();
    chunk_kv_k<<<dim3(3, NC, NH), thr>>>();
    {
        int total = NH * CHUNK_ELT + NH * DP;       // 224640
        prefix_k<<<(total + 255) / 256, 256>>>();
    }
    chunk_attn_k<<<dim3(NC, NH), thr, attn_smem>>>();
    tf32_gemm<<<dim3(12, 8), thr>>>(dY, Wo, out, DM, DM);
}

// round 5
// speedup vs baseline: 1.5422x; 1.5422x over previous
#include <cuda_runtime.h>
#include <cstdint>

// Problem constants
#define LL   1024   // sequence length
#define DM   768    // d_model
#define NH   12     // heads
#define FD   16     // feature dim per head
#define HD   64     // head dim (v)
#define CH   64     // chunk length
#define NC   16     // number of chunks (LL/CH)
#define DP   288    // padded expanded feature dim (273 -> 288)
#define CHUNK_ELT (DP*HD)   // 18432 floats per (head,chunk) state

// Scratch (static device globals; no allocation)
__device__ float g_Q   [LL * NH * FD];        // (t, h*16+f)
__device__ float g_K   [LL * NH * FD];
__device__ float g_V   [LL * DM];             // (t, h*64+d)
__device__ float g_Qf  [NH * NC * CHUNK_ELT]; // [h][c][n][i]
__device__ float g_Kf  [NH * NC * CHUNK_ELT];
__device__ float g_S   [NH * NC * CHUNK_ELT]; // per-chunk KV sums -> exclusive prefix
__device__ float g_ksum[NH * NC * DP];        // per-chunk k-feature sums -> exclusive prefix
__device__ float g_Y   [LL * DM];             // attention output before Wo

// ---------------------------------------------------------------------------
// TF32 helpers
// ---------------------------------------------------------------------------
__device__ __forceinline__ uint32_t f2tf32(float x) {
    uint32_t r;
    asm volatile("cvt.rna.tf32.f32 %0, %1;" : "=r"(r) : "f"(x));
    return r;
}

__device__ __forceinline__ void mma_tf32(float c[4], const uint32_t a[4], const uint32_t b[2]) {
    asm volatile("mma.sync.aligned.m16n8k8.row.col.f32.tf32.tf32.f32 "
                 "{%0,%1,%2,%3}, {%4,%5,%6,%7}, {%8,%9}, {%0,%1,%2,%3};\n"
                 : "+f"(c[0]), "+f"(c[1]), "+f"(c[2]), "+f"(c[3])
                 : "r"(a[0]), "r"(a[1]), "r"(a[2]), "r"(a[3]),
                   "r"(b[0]), "r"(b[1]));
}

// Per-buffer smem layout (uint32): Ah[128*20] Al[128*20] Bh[64*20] Bl[64*20]
#define SMBUF 7680
#define SMEM_GEMM_BYTES (2 * SMBUF * 4)   // 61440

// ---------------------------------------------------------------------------
// 3xTF32 tensor-core GEMM body: C[128 x 64] tile of A[1024 x K] @ B[K x N].
// 256 threads = 8 warps (4x2), warp tile 32x32 (2x4 m16n8k8 subtiles).
// C = Ahi*Bhi + Ahi*Blo + Alo*Bhi  (~fp32-exact).
// Double-buffered smem; next tile prefetched to registers during mma.
// smem stride 20 == 4 (mod 32): conflict-free fragment LDS.
// ---------------------------------------------------------------------------
__device__ __forceinline__ void tf32_body(const float* __restrict__ A,
                                          const float* __restrict__ B,
                                          float* __restrict__ C,
                                          int N, int K, int bm, int bn,
                                          uint32_t* sm) {
    const int tid  = threadIdx.x;
    const int lane = tid & 31, w = tid >> 5;
    const int wm = w >> 1, wn = w & 1;
    const int gid = lane >> 2, tig = lane & 3;
    const int r0  = tid >> 2, c0 = (tid & 3) * 4;   // A staging: rows r0, r0+64
    const int kkB = tid >> 4, n4 = (tid & 15) * 4;  // B staging

    float acc[2][4][4] = {};
    const int nit = K / 16;

    float4 a0v = *(const float4*)&A[(bm + r0) * K + c0];
    float4 a1v = *(const float4*)&A[(bm + r0 + 64) * K + c0];
    float4 bv  = *(const float4*)&B[kkB * N + bn + n4];

    // convert + store one stage into a buffer
    auto cvst = [&](uint32_t* buf, float4 A0, float4 A1, float4 Bv) {
        uint32_t* Ah = buf;
        uint32_t* Al = buf + 2560;
        uint32_t* Bh = buf + 5120;
        uint32_t* Bl = buf + 6400;
        float av0[4] = { A0.x, A0.y, A0.z, A0.w };
        float av1[4] = { A1.x, A1.y, A1.z, A1.w };
        float bvv[4] = { Bv.x, Bv.y, Bv.z, Bv.w };
#pragma unroll
        for (int j = 0; j < 4; j++) {
            uint32_t h0 = f2tf32(av0[j]);
            Ah[r0 * 20 + c0 + j] = h0;
            Al[r0 * 20 + c0 + j] = f2tf32(av0[j] - __uint_as_float(h0));
            uint32_t h1 = f2tf32(av1[j]);
            Ah[(r0 + 64) * 20 + c0 + j] = h1;
            Al[(r0 + 64) * 20 + c0 + j] = f2tf32(av1[j] - __uint_as_float(h1));
            uint32_t hb = f2tf32(bvv[j]);
            Bh[(n4 + j) * 20 + kkB] = hb;
            Bl[(n4 + j) * 20 + kkB] = f2tf32(bvv[j] - __uint_as_float(hb));
        }
    };

    cvst(sm, a0v, a1v, bv);
    __syncthreads();

    for (int it = 0; it < nit; it++) {
        uint32_t* cbuf = sm + (it & 1) * SMBUF;
        if (it + 1 < nit) {                      // prefetch next stage to regs
            int k0 = (it + 1) * 16;
            a0v = *(const float4*)&A[(bm + r0) * K + k0 + c0];
            a1v = *(const float4*)&A[(bm + r0 + 64) * K + k0 + c0];
            bv  = *(const float4*)&B[(k0 + kkB) * N + bn + n4];
        }
        uint32_t* Ah = cbuf;
        uint32_t* Al = cbuf + 2560;
        uint32_t* Bh = cbuf + 5120;
        uint32_t* Bl = cbuf + 6400;
#pragma unroll
        for (int ks = 0; ks < 2; ks++) {
            const int kb = ks * 8;
            uint32_t ah[2][4], al[2][4], bh[4][2], bl[4][2];
#pragma unroll
            for (int mt = 0; mt < 2; mt++) {
                int rb = wm * 32 + mt * 16;
                ah[mt][0] = Ah[(rb + gid)     * 20 + kb + tig];
                ah[mt][1] = Ah[(rb + gid + 8) * 20 + kb + tig];
                ah[mt][2] = Ah[(rb + gid)     * 20 + kb + tig + 4];
                ah[mt][3] = Ah[(rb + gid + 8) * 20 + kb + tig + 4];
                al[mt][0] = Al[(rb + gid)     * 20 + kb + tig];
                al[mt][1] = Al[(rb + gid + 8) * 20 + kb + tig];
                al[mt][2] = Al[(rb + gid)     * 20 + kb + tig + 4];
                al[mt][3] = Al[(rb + gid + 8) * 20 + kb + tig + 4];
            }
#pragma unroll
            for (int nt = 0; nt < 4; nt++) {
                int nb = wn * 32 + nt * 8;
                bh[nt][0] = Bh[(nb + gid) * 20 + kb + tig];
                bh[nt][1] = Bh[(nb + gid) * 20 + kb + tig + 4];
                bl[nt][0] = Bl[(nb + gid) * 20 + kb + tig];
                bl[nt][1] = Bl[(nb + gid) * 20 + kb + tig + 4];
            }
#pragma unroll
            for (int mt = 0; mt < 2; mt++)
#pragma unroll
                for (int nt = 0; nt < 4; nt++) {
                    mma_tf32(acc[mt][nt], ah[mt], bh[nt]);
                    mma_tf32(acc[mt][nt], ah[mt], bl[nt]);
                    mma_tf32(acc[mt][nt], al[mt], bh[nt]);
                }
        }
        if (it + 1 < nit) cvst(sm + ((it + 1) & 1) * SMBUF, a0v, a1v, bv);
        __syncthreads();
    }

#pragma unroll
    for (int mt = 0; mt < 2; mt++)
#pragma unroll
        for (int nt = 0; nt < 4; nt++) {
            int row = bm + wm * 32 + mt * 16 + gid;
            int col = bn + wn * 32 + nt * 8 + tig * 2;
            *(float2*)&C[row * N + col]       = make_float2(acc[mt][nt][0], acc[mt][nt][1]);
            *(float2*)&C[(row + 8) * N + col] = make_float2(acc[mt][nt][2], acc[mt][nt][3]);
        }
}

// Fused Q/K/V projection: grid (18, 8). x<3 -> Wq, x<6 -> Wk, else Wv.
__global__ __launch_bounds__(256) void qkv_gemm(const float* __restrict__ hs,
                                                const float* __restrict__ Wq,
                                                const float* __restrict__ Wk,
                                                const float* __restrict__ Wv) {
    extern __shared__ uint32_t smext[];
    const int bx = blockIdx.x, bm = blockIdx.y * 128;
    const float* B; float* C; int N, bn;
    if (bx < 3)      { B = Wq; C = g_Q; N = NH * FD; bn = bx * 64; }
    else if (bx < 6) { B = Wk; C = g_K; N = NH * FD; bn = (bx - 3) * 64; }
    else             { B = Wv; C = g_V; N = DM;      bn = (bx - 6) * 64; }
    tf32_body(hs, B, C, N, DM, bm, bn, smext);
}

// Output projection: grid (12, 8).
__global__ __launch_bounds__(256) void o_gemm(const float* __restrict__ Wo,
                                              float* __restrict__ out) {
    extern __shared__ uint32_t smext[];
    tf32_body(g_Y, Wo, out, DM, DM, blockIdx.y * 128, blockIdx.x * 64, smext);
}

// ---------------------------------------------------------------------------
// Featurize: taylor_exp_feature_map (Q and K in one launch via blockIdx.z).
// dst[h][c][n][i]: n=0 -> 1 ; 1..16 -> x/2 ; 17..272 -> x_a*x_b/(4*sqrt2); pad 0
// ---------------------------------------------------------------------------
__global__ __launch_bounds__(256) void featurize_k() {
    const int which = blockIdx.z;
    const float* __restrict__ src = which ? g_K : g_Q;
    float* __restrict__ dst = which ? g_Kf : g_Qf;
    const int c = blockIdx.x, h = blockIdx.y;
    __shared__ float xs[64][17];
    const int tid = threadIdx.x;
    for (int idx = tid; idx < CH * FD; idx += 256) {
        int i = idx >> 4, f = idx & 15;
        xs[i][f] = src[(c * CH + i) * (NH * FD) + h * FD + f];
    }
    __syncthreads();
    float* out = dst + (h * NC + c) * CHUNK_ELT;
    const float S1 = 0.5f;                    // 1/RRD
    const float S2 = 0.17677669529663687f;    // 1/(sqrt(2)*sqrt(16))
    for (int idx = tid; idx < CHUNK_ELT; idx += 256) {
        int n = idx >> 6, i = idx & 63;
        float v;
        if (n == 0)        v = 1.0f;
        else if (n <= 16)  v = xs[i][n - 1] * S1;
        else if (n <= 272) { int p = n - 17; v = xs[i][p >> 4] * xs[i][p & 15] * S2; }
        else               v = 0.0f;
        out[idx] = v;
    }
}

// ---------------------------------------------------------------------------
// Per-chunk KV state: S[h][c][n][d] = sum_i Kf[h][c][n][i] * V[c*64+i][h*64+d]
// Also ksum[h][c][n] = sum_i Kf[n][i].  Grid: (3 n-tiles of 96, NC, NH).
// ---------------------------------------------------------------------------
__global__ __launch_bounds__(256) void chunk_kv_k() {
    const int nt = blockIdx.x, c = blockIdx.y, h = blockIdx.z;
    __shared__ __align__(16) float Ks[96 * 64];
    __shared__ __align__(16) float Vs[64 * 64];
    const int tid = threadIdx.x;
    const float* kf = g_Kf + ((h * NC + c) * DP + nt * 96) * 64;
    for (int idx = tid; idx < 96 * 64 / 4; idx += 256)
        ((float4*)Ks)[idx] = ((const float4*)kf)[idx];
    const float* vp = g_V + (c * CH) * DM + h * HD;
    for (int idx = tid; idx < 64 * 16; idx += 256) {
        int i = idx >> 4, dd = idx & 15;
        ((float4*)Vs)[i * 16 + dd] = ((const float4*)(vp + i * DM))[dd];
    }
    __syncthreads();
    const int ty = tid >> 4, tx = tid & 15;
    const int nb = ty * 6;
    float acc[6][4] = {};
    for (int i = 0; i < 64; i++) {
        float4 v4 = *(const float4*)&Vs[i * 64 + tx * 4];
#pragma unroll
        for (int m = 0; m < 6; m++) {
            float a = Ks[(nb + m) * 64 + i];
            acc[m][0] += a * v4.x; acc[m][1] += a * v4.y;
            acc[m][2] += a * v4.z; acc[m][3] += a * v4.w;
        }
    }
    float* sp = g_S + ((h * NC + c) * DP + nt * 96) * 64;
#pragma unroll
    for (int m = 0; m < 6; m++) {
        float4 o = make_float4(acc[m][0], acc[m][1], acc[m][2], acc[m][3]);
        *(float4*)&sp[(nb + m) * 64 + tx * 4] = o;
    }
    if (tid < 96) {
        float s = 0.f;
        for (int k = 0; k < 64; k++) s += Ks[tid * 64 + ((tid + k) & 63)];
        g_ksum[(h * NC + c) * DP + nt * 96 + tid] = s;
    }
}

// ---------------------------------------------------------------------------
// Exclusive prefix over chunks (in place), for g_S and g_ksum.
// ---------------------------------------------------------------------------
__global__ __launch_bounds__(256) void prefix_k() {
    const int gid = blockIdx.x * 256 + threadIdx.x;
    const int NS = NH * CHUNK_ELT;  // 221184
    if (gid < NS) {
        int h = gid / CHUNK_ELT, e = gid % CHUNK_ELT;
        float* base = g_S + h * NC * CHUNK_ELT + e;
        float acc = 0.f;
#pragma unroll
        for (int c = 0; c < NC; c++) {
            float v = base[c * CHUNK_ELT];
            base[c * CHUNK_ELT] = acc;
            acc += v;
        }
    } else {
        int j = gid - NS;
        if (j < NH * DP) {
            int h = j / DP, n = j % DP;
            float* base = g_ksum + h * NC * DP + n;
            float acc = 0.f;
#pragma unroll
            for (int c = 0; c < NC; c++) {
                float v = base[c * DP];
                base[c * DP] = acc;
                acc += v;
            }
        }
    }
}

// ---------------------------------------------------------------------------
// Chunk attention: per (chunk, head) block.
//   A[i][j]   = sum_n Qf[n][i]*Kf[n][j]   (masked j<=i)
//   num[i][d] = sum_n Qf[n][i]*Sprev[n][d] + sum_j A[i][j]*V[j][d]
//   den[i]    = sum_n Qf[n][i]*ksumprev[n] + sum_j A[i][j]
//   Y[t][h*64+d] = num/(den+1e-12)
// ---------------------------------------------------------------------------
__global__ __launch_bounds__(256) void chunk_attn_k() {
    const int c = blockIdx.x, h = blockIdx.y;
    extern __shared__ __align__(16) float sm[];
    float* Qs  = sm;                 // [n][i] 288x64
    float* Ks  = sm + CHUNK_ELT;     // [n][j] 288x64
    float* Vs  = sm + 2 * CHUNK_ELT; // [j][d] 64x64
    float* Asm = Vs + 64 * 64;       // [i][j] 64x64
    const int tid = threadIdx.x;

    const float* qf = g_Qf + (h * NC + c) * CHUNK_ELT;
    const float* kf = g_Kf + (h * NC + c) * CHUNK_ELT;
    for (int idx = tid; idx < CHUNK_ELT / 4; idx += 256) {
        ((float4*)Qs)[idx] = ((const float4*)qf)[idx];
        ((float4*)Ks)[idx] = ((const float4*)kf)[idx];
    }
    const float* vp = g_V + (c * CH) * DM + h * HD;
    for (int idx = tid; idx < 64 * 16; idx += 256) {
        int i = idx >> 4, dd = idx & 15;
        ((float4*)Vs)[i * 16 + dd] = ((const float4*)(vp + i * DM))[dd];
    }
    __syncthreads();

    const int ty = tid >> 4, tx = tid & 15;
    const int i0 = ty * 4, c0 = tx * 4;
    const float* Sx = g_S + (h * NC + c) * CHUNK_ELT;
    const float* kx = g_ksum + (h * NC + c) * DP;

    float aA[4][4] = {};
    float aN[4][4] = {};
    float aD[4] = {};

#pragma unroll 2
    for (int n = 0; n < DP; n++) {
        float4 q4 = *(const float4*)&Qs[n * 64 + i0];
        float4 k4 = *(const float4*)&Ks[n * 64 + c0];
        float4 s4 = __ldg((const float4*)(Sx + n * 64 + c0));
        float ks  = __ldg(kx + n);
        float q[4] = { q4.x, q4.y, q4.z, q4.w };
        float kk[4] = { k4.x, k4.y, k4.z, k4.w };
        float ss[4] = { s4.x, s4.y, s4.z, s4.w };
#pragma unroll
        for (int m = 0; m < 4; m++) {
#pragma unroll
            for (int j = 0; j < 4; j++) {
                aA[m][j] += q[m] * kk[j];
                aN[m][j] += q[m] * ss[j];
            }
            aD[m] += q[m] * ks;
        }
    }

#pragma unroll
    for (int m = 0; m < 4; m++) {
        int ig = i0 + m;
        float4 r;
        r.x = (c0 + 0 <= ig) ? aA[m][0] : 0.0f;
        r.y = (c0 + 1 <= ig) ? aA[m][1] : 0.0f;
        r.z = (c0 + 2 <= ig) ? aA[m][2] : 0.0f;
        r.w = (c0 + 3 <= ig) ? aA[m][3] : 0.0f;
        *(float4*)&Asm[ig * 64 + c0] = r;
    }
    __syncthreads();

    for (int j = 0; j < 64; j++) {
        float4 v4 = *(const float4*)&Vs[j * 64 + c0];
#pragma unroll
        for (int m = 0; m < 4; m++) {
            float a = Asm[(i0 + m) * 64 + j];
            aN[m][0] += a * v4.x; aN[m][1] += a * v4.y;
            aN[m][2] += a * v4.z; aN[m][3] += a * v4.w;
            aD[m] += a;
        }
    }

    float* yp = g_Y + (c * CH) * DM + h * HD;
#pragma unroll
    for (int m = 0; m < 4; m++) {
        float inv = 1.0f / (aD[m] + 1e-12f);
        float4 o = make_float4(aN[m][0] * inv, aN[m][1] * inv,
                               aN[m][2] * inv, aN[m][3] * inv);
        *(float4*)&yp[(i0 + m) * DM + c0] = o;
    }
}

// ---------------------------------------------------------------------------
extern "C" void kernel_launch(void* const* d_in, const int* in_sizes, int n_in,
                              void* d_out, int out_size) {
    const float* hs = (const float*)d_in[0];
    const float* Wq = (const float*)d_in[1];
    const float* Wk = (const float*)d_in[2];
    const float* Wv = (const float*)d_in[3];
    const float* Wo = (const float*)d_in[4];
    float* out = (float*)d_out;

    const int attn_smem = (2 * CHUNK_ELT + 2 * 64 * 64) * 4;  // 180224 B
    cudaFuncSetAttribute(chunk_attn_k, cudaFuncAttributeMaxDynamicSharedMemorySize, attn_smem);
    cudaFuncSetAttribute(qkv_gemm, cudaFuncAttributeMaxDynamicSharedMemorySize, SMEM_GEMM_BYTES);
    cudaFuncSetAttribute(o_gemm,   cudaFuncAttributeMaxDynamicSharedMemorySize, SMEM_GEMM_BYTES);

    dim3 thr(256);
    qkv_gemm<<<dim3(18, 8), thr, SMEM_GEMM_BYTES>>>(hs, Wq, Wk, Wv);
    featurize_k<<<dim3(NC, NH, 2), thr>>>();
    chunk_kv_k<<<dim3(3, NC, NH), thr>>>();
    {
        int total = NH * CHUNK_ELT + NH * DP;       // 224640
        prefix_k<<<(total + 255) / 256, 256>>>();
    }
    chunk_attn_k<<<dim3(NC, NH), thr, attn_smem>>>();
    o_gemm<<<dim3(12, 8), thr, SMEM_GEMM_BYTES>>>(Wo, out);
}

// round 6
// speedup vs baseline: 2.1613x; 1.4014x over previous
#include <cuda_runtime.h>
#include <cstdint>

// Problem constants
#define LL   1024   // sequence length
#define DM   768    // d_model
#define NH   12     // heads
#define FD   16     // feature dim per head
#define HD   64     // head dim (v)
#define CH   64     // chunk length
#define NC   16     // number of chunks (LL/CH)
#define DP   288    // padded expanded feature dim (273 -> 288)
#define CHUNK_ELT (DP*HD)   // 18432 floats per (head,chunk) state

// Scratch (static device globals; no allocation)
__device__ float g_Q   [LL * NH * FD];
__device__ float g_K   [LL * NH * FD];
__device__ float g_V   [LL * DM];
__device__ float g_Qf  [NH * NC * CHUNK_ELT]; // [h][c][n][i]
__device__ float g_Kf  [NH * NC * CHUNK_ELT];
__device__ float g_S   [NH * NC * CHUNK_ELT]; // per-chunk KV sums -> exclusive prefix
__device__ float g_ksum[NH * NC * DP];
__device__ float g_Y   [LL * DM];

// ---------------------------------------------------------------------------
// TF32 helpers
// ---------------------------------------------------------------------------
__device__ __forceinline__ uint32_t f2tf32(float x) {
    uint32_t r;
    asm volatile("cvt.rna.tf32.f32 %0, %1;" : "=r"(r) : "f"(x));
    return r;
}
__device__ __forceinline__ void split2(float x, uint32_t& hi, uint32_t& lo) {
    hi = f2tf32(x);
    lo = f2tf32(x - __uint_as_float(hi));
}
__device__ __forceinline__ void mma_tf32(float c[4], const uint32_t a[4], const uint32_t b[2]) {
    asm volatile("mma.sync.aligned.m16n8k8.row.col.f32.tf32.tf32.f32 "
                 "{%0,%1,%2,%3}, {%4,%5,%6,%7}, {%8,%9}, {%0,%1,%2,%3};\n"
                 : "+f"(c[0]), "+f"(c[1]), "+f"(c[2]), "+f"(c[3])
                 : "r"(a[0]), "r"(a[1]), "r"(a[2]), "r"(a[3]),
                   "r"(b[0]), "r"(b[1]));
}
#define ONE_TF32 0x3f800000u

// ===========================================================================
// 3xTF32 projection GEMM (unchanged from round 5)
// ===========================================================================
#define SMBUF 7680
#define SMEM_GEMM_BYTES (2 * SMBUF * 4)

__device__ __forceinline__ void tf32_body(const float* __restrict__ A,
                                          const float* __restrict__ B,
                                          float* __restrict__ C,
                                          int N, int K, int bm, int bn,
                                          uint32_t* sm) {
    const int tid  = threadIdx.x;
    const int lane = tid & 31, w = tid >> 5;
    const int wm = w >> 1, wn = w & 1;
    const int gid = lane >> 2, tig = lane & 3;
    const int r0  = tid >> 2, c0 = (tid & 3) * 4;
    const int kkB = tid >> 4, n4 = (tid & 15) * 4;

    float acc[2][4][4] = {};
    const int nit = K / 16;

    float4 a0v = *(const float4*)&A[(bm + r0) * K + c0];
    float4 a1v = *(const float4*)&A[(bm + r0 + 64) * K + c0];
    float4 bv  = *(const float4*)&B[kkB * N + bn + n4];

    auto cvst = [&](uint32_t* buf, float4 A0, float4 A1, float4 Bv) {
        uint32_t* Ah = buf;
        uint32_t* Al = buf + 2560;
        uint32_t* Bh = buf + 5120;
        uint32_t* Bl = buf + 6400;
        float av0[4] = { A0.x, A0.y, A0.z, A0.w };
        float av1[4] = { A1.x, A1.y, A1.z, A1.w };
        float bvv[4] = { Bv.x, Bv.y, Bv.z, Bv.w };
#pragma unroll
        for (int j = 0; j < 4; j++) {
            uint32_t h0, l0; split2(av0[j], h0, l0);
            Ah[r0 * 20 + c0 + j] = h0; Al[r0 * 20 + c0 + j] = l0;
            uint32_t h1, l1; split2(av1[j], h1, l1);
            Ah[(r0 + 64) * 20 + c0 + j] = h1; Al[(r0 + 64) * 20 + c0 + j] = l1;
            uint32_t hb, lb; split2(bvv[j], hb, lb);
            Bh[(n4 + j) * 20 + kkB] = hb; Bl[(n4 + j) * 20 + kkB] = lb;
        }
    };

    cvst(sm, a0v, a1v, bv);
    __syncthreads();

    for (int it = 0; it < nit; it++) {
        uint32_t* cbuf = sm + (it & 1) * SMBUF;
        if (it + 1 < nit) {
            int k0 = (it + 1) * 16;
            a0v = *(const float4*)&A[(bm + r0) * K + k0 + c0];
            a1v = *(const float4*)&A[(bm + r0 + 64) * K + k0 + c0];
            bv  = *(const float4*)&B[(k0 + kkB) * N + bn + n4];
        }
        uint32_t* Ah = cbuf;
        uint32_t* Al = cbuf + 2560;
        uint32_t* Bh = cbuf + 5120;
        uint32_t* Bl = cbuf + 6400;
#pragma unroll
        for (int ks = 0; ks < 2; ks++) {
            const int kb = ks * 8;
            uint32_t ah[2][4], al[2][4], bh[4][2], bl[4][2];
#pragma unroll
            for (int mt = 0; mt < 2; mt++) {
                int rb = wm * 32 + mt * 16;
                ah[mt][0] = Ah[(rb + gid)     * 20 + kb + tig];
                ah[mt][1] = Ah[(rb + gid + 8) * 20 + kb + tig];
                ah[mt][2] = Ah[(rb + gid)     * 20 + kb + tig + 4];
                ah[mt][3] = Ah[(rb + gid + 8) * 20 + kb + tig + 4];
                al[mt][0] = Al[(rb + gid)     * 20 + kb + tig];
                al[mt][1] = Al[(rb + gid + 8) * 20 + kb + tig];
                al[mt][2] = Al[(rb + gid)     * 20 + kb + tig + 4];
                al[mt][3] = Al[(rb + gid + 8) * 20 + kb + tig + 4];
            }
#pragma unroll
            for (int nt = 0; nt < 4; nt++) {
                int nb = wn * 32 + nt * 8;
                bh[nt][0] = Bh[(nb + gid) * 20 + kb + tig];
                bh[nt][1] = Bh[(nb + gid) * 20 + kb + tig + 4];
                bl[nt][0] = Bl[(nb + gid) * 20 + kb + tig];
                bl[nt][1] = Bl[(nb + gid) * 20 + kb + tig + 4];
            }
#pragma unroll
            for (int mt = 0; mt < 2; mt++)
#pragma unroll
                for (int nt = 0; nt < 4; nt++) {
                    mma_tf32(acc[mt][nt], ah[mt], bh[nt]);
                    mma_tf32(acc[mt][nt], ah[mt], bl[nt]);
                    mma_tf32(acc[mt][nt], al[mt], bh[nt]);
                }
        }
        if (it + 1 < nit) cvst(sm + ((it + 1) & 1) * SMBUF, a0v, a1v, bv);
        __syncthreads();
    }

#pragma unroll
    for (int mt = 0; mt < 2; mt++)
#pragma unroll
        for (int nt = 0; nt < 4; nt++) {
            int row = bm + wm * 32 + mt * 16 + gid;
            int col = bn + wn * 32 + nt * 8 + tig * 2;
            *(float2*)&C[row * N + col]       = make_float2(acc[mt][nt][0], acc[mt][nt][1]);
            *(float2*)&C[(row + 8) * N + col] = make_float2(acc[mt][nt][2], acc[mt][nt][3]);
        }
}

__global__ __launch_bounds__(256) void qkv_gemm(const float* __restrict__ hs,
                                                const float* __restrict__ Wq,
                                                const float* __restrict__ Wk,
                                                const float* __restrict__ Wv) {
    extern __shared__ uint32_t smext[];
    const int bx = blockIdx.x, bm = blockIdx.y * 128;
    const float* B; float* C; int N, bn;
    if (bx < 3)      { B = Wq; C = g_Q; N = NH * FD; bn = bx * 64; }
    else if (bx < 6) { B = Wk; C = g_K; N = NH * FD; bn = (bx - 3) * 64; }
    else             { B = Wv; C = g_V; N = DM;      bn = (bx - 6) * 64; }
    tf32_body(hs, B, C, N, DM, bm, bn, smext);
}

__global__ __launch_bounds__(256) void o_gemm(const float* __restrict__ Wo,
                                              float* __restrict__ out) {
    extern __shared__ uint32_t smext[];
    tf32_body(g_Y, Wo, out, DM, DM, blockIdx.y * 128, blockIdx.x * 64, smext);
}

// ===========================================================================
// Featurize: branch-free float4 loops. dst[h][c][n][i].
// ===========================================================================
__global__ __launch_bounds__(256) void featurize_k() {
    const int which = blockIdx.z;
    const float* __restrict__ src = which ? g_K : g_Q;
    float* __restrict__ dst = which ? g_Kf : g_Qf;
    const int c = blockIdx.x, h = blockIdx.y;
    __shared__ float xs[64][17];
    const int tid = threadIdx.x;
    for (int idx = tid; idx < CH * FD; idx += 256) {
        int i = idx >> 4, f = idx & 15;
        xs[i][f] = src[(c * CH + i) * (NH * FD) + h * FD + f];
    }
    __syncthreads();
    float* out = dst + (h * NC + c) * CHUNK_ELT;
    const float S1 = 0.5f;
    const float S2 = 0.17677669529663687f;

    // row 0: ones (16 float4)
    if (tid < 16) *(float4*)&out[tid * 4] = make_float4(1.f, 1.f, 1.f, 1.f);
    // pad rows 273..287: zeros (240 float4)
    if (tid < 240) ((float4*)(out + 273 * 64))[tid] = make_float4(0.f, 0.f, 0.f, 0.f);
    // linear rows 1..16: 256 float4
    {
        int n = 1 + (tid >> 4), i4 = (tid & 15) * 4;
        float4 v;
        v.x = xs[i4 + 0][n - 1] * S1;
        v.y = xs[i4 + 1][n - 1] * S1;
        v.z = xs[i4 + 2][n - 1] * S1;
        v.w = xs[i4 + 3][n - 1] * S1;
        *(float4*)&out[n * 64 + i4] = v;
    }
    // quadratic rows 17..272: 4096 float4
    float4* outq = (float4*)(out + 17 * 64);
#pragma unroll
    for (int l = 0; l < 16; l++) {
        int fi = tid + l * 256;
        int p = fi >> 4, i4 = (fi & 15) * 4;
        int a = p >> 4, b = p & 15;
        float4 v;
        v.x = xs[i4 + 0][a] * xs[i4 + 0][b] * S2;
        v.y = xs[i4 + 1][a] * xs[i4 + 1][b] * S2;
        v.z = xs[i4 + 2][a] * xs[i4 + 2][b] * S2;
        v.w = xs[i4 + 3][a] * xs[i4 + 3][b] * S2;
        outq[fi] = v;
    }
}

// ===========================================================================
// chunk_kv (tensor): S[144x64 half] = Kf @ V, ksum via ones-B trick.
// grid (2, NC, NH), 288 threads (9 warps, 16 rows each).
// ===========================================================================
#define KV_SMEM ((144 * 72 + 64 * 72) * 4)
__global__ __launch_bounds__(288) void chunk_kv_k() {
    extern __shared__ __align__(16) float smv[];
    float* Kt = smv;             // [row][i] stride 72
    float* Vs = smv + 144 * 72;  // [i][d]  stride 72
    const int half = blockIdx.x, c = blockIdx.y, h = blockIdx.z;
    const int tid = threadIdx.x, w = tid >> 5, lane = tid & 31;
    const int gid = lane >> 2, tig = lane & 3;
    const int base = (h * NC + c) * CHUNK_ELT;

    const float4* kf4 = (const float4*)(g_Kf + base + half * 144 * 64);
#pragma unroll
    for (int l = 0; l < 8; l++) {
        int fi = tid + l * 288;
        int r = fi >> 4, c4 = (fi & 15) * 4;
        *(float4*)&Kt[r * 72 + c4] = kf4[fi];
    }
#pragma unroll
    for (int l = 0; l < 4; l++) {
        int fi = tid + l * 288;
        if (fi < 1024) {
            int j = fi >> 4, d4 = (fi & 15) * 4;
            *(float4*)&Vs[j * 72 + d4] = *(const float4*)&g_V[(c * CH + j) * DM + h * HD + d4];
        }
    }
    __syncthreads();

    float acc[8][4] = {};
    float acck[4] = {};
    const uint32_t ones[2] = { ONE_TF32, ONE_TF32 };
    const int rbl = w * 16;

#pragma unroll
    for (int ks = 0; ks < 8; ks++) {
        const int kb = ks * 8;
        uint32_t ah[4], al[4];
        split2(Kt[(rbl + gid)     * 72 + kb + tig],     ah[0], al[0]);
        split2(Kt[(rbl + gid + 8) * 72 + kb + tig],     ah[1], al[1]);
        split2(Kt[(rbl + gid)     * 72 + kb + tig + 4], ah[2], al[2]);
        split2(Kt[(rbl + gid + 8) * 72 + kb + tig + 4], ah[3], al[3]);
#pragma unroll
        for (int nt = 0; nt < 8; nt++) {
            uint32_t bh[2], bl[2];
            split2(Vs[(kb + tig)     * 72 + nt * 8 + gid], bh[0], bl[0]);
            split2(Vs[(kb + tig + 4) * 72 + nt * 8 + gid], bh[1], bl[1]);
            mma_tf32(acc[nt], ah, bh);
            mma_tf32(acc[nt], ah, bl);
            mma_tf32(acc[nt], al, bh);
        }
        mma_tf32(acck, ah, ones);
        mma_tf32(acck, al, ones);
    }

    float* sp = g_S + base;
    const int grow0 = half * 144 + rbl + gid, grow1 = grow0 + 8;
#pragma unroll
    for (int nt = 0; nt < 8; nt++) {
        int col = nt * 8 + tig * 2;
        *(float2*)&sp[grow0 * 64 + col] = make_float2(acc[nt][0], acc[nt][1]);
        *(float2*)&sp[grow1 * 64 + col] = make_float2(acc[nt][2], acc[nt][3]);
    }
    if (tig == 0) {
        float* kp = g_ksum + (h * NC + c) * DP;
        kp[grow0] = acck[0];
        kp[grow1] = acck[2];
    }
}

// ===========================================================================
// Exclusive prefix over chunks (in place), for g_S and g_ksum.
// ===========================================================================
__global__ __launch_bounds__(256) void prefix_k() {
    const int gid = blockIdx.x * 256 + threadIdx.x;
    const int NS = NH * CHUNK_ELT;
    if (gid < NS) {
        int h = gid / CHUNK_ELT, e = gid % CHUNK_ELT;
        float* base = g_S + h * NC * CHUNK_ELT + e;
        float acc = 0.f;
#pragma unroll
        for (int c = 0; c < NC; c++) {
            float v = base[c * CHUNK_ELT];
            base[c * CHUNK_ELT] = acc;
            acc += v;
        }
    } else {
        int j = gid - NS;
        if (j < NH * DP) {
            int h = j / DP, n = j % DP;
            float* base = g_ksum + h * NC * DP + n;
            float acc = 0.f;
#pragma unroll
            for (int c = 0; c < NC; c++) {
                float v = base[c * DP];
                base[c * DP] = acc;
                acc += v;
            }
        }
    }
}

// ===========================================================================
// chunk_attn (tensor): per (c,h) block, 256 thr, 8 warps (wm 0..1 x wn 0..3).
// Mainloop over 18 feature-slices: A += Qf^T Kf ; num += Qf^T Sprev ;
// den += Qf^T ksum (broadcast-B, wn==0 warps). Then mask A -> smem,
// phase 2: num += A@V ; den += rowsum(A) (ones-B). Divide, store g_Y.
// ===========================================================================
#define SLICE_SZ (3 * 16 * 72 + 16)     // 3472 floats
#define ATTN_SMEM ((64*72 + 64*72 + 64 + 2*SLICE_SZ) * 4)  // 64896 B
__global__ __launch_bounds__(256) void chunk_attn_k() {
    extern __shared__ __align__(16) float sm[];
    float* Vs   = sm;                 // [j][d] 64x72
    float* Asm  = sm + 64 * 72;       // [i][j] 64x72
    float* den  = Asm + 64 * 72;      // [64]
    float* bufs = den + 64;           // 2 x SLICE_SZ

    const int c = blockIdx.x, h = blockIdx.y;
    const int tid = threadIdx.x, w = tid >> 5, lane = tid & 31;
    const int wm = w >> 2, wn = w & 3;
    const int gid = lane >> 2, tig = lane & 3;

    const int qbase = (h * NC + c) * CHUNK_ELT;
    const int kbase = (h * NC + c) * DP;
    const int sr = tid >> 4, sc4 = (tid & 15) * 4;   // staging coords

    // stage V
#pragma unroll
    for (int l = 0; l < 4; l++) {
        int fi = tid + l * 256;
        int j = fi >> 4, d4 = (fi & 15) * 4;
        *(float4*)&Vs[j * 72 + d4] = *(const float4*)&g_V[(c * CH + j) * DM + h * HD + d4];
    }

    // stage slice 0
    {
        int off = sr * 64 + sc4;
        *(float4*)&bufs[sr * 72 + sc4]            = *(const float4*)&g_Qf[qbase + off];
        *(float4*)&bufs[1152 + sr * 72 + sc4]     = *(const float4*)&g_Kf[qbase + off];
        *(float4*)&bufs[2304 + sr * 72 + sc4]     = *(const float4*)&g_S[qbase + off];
        if (tid < 16) bufs[3456 + tid] = g_ksum[kbase + tid];
    }
    __syncthreads();

    float aA[2][2][4] = {};   // scores  (rows wm*32+mt*16, cols wn*16+nt*8)
    float aN[2][2][4] = {};   // numerator
    float aD[2][4] = {};      // denominator (wn==0 warps only)
    const uint32_t ones[2] = { ONE_TF32, ONE_TF32 };

    for (int s = 0; s < 18; s++) {
        float* cb = bufs + (s & 1) * SLICE_SZ;
        float4 pq, pk, ps; float pks = 0.f;
        if (s + 1 < 18) {
            int off = (s + 1) * 16 * 64 + sr * 64 + sc4;
            pq = *(const float4*)&g_Qf[qbase + off];
            pk = *(const float4*)&g_Kf[qbase + off];
            ps = *(const float4*)&g_S[qbase + off];
            if (tid < 16) pks = g_ksum[kbase + (s + 1) * 16 + tid];
        }
        float* Qsl = cb;
        float* Ksl = cb + 1152;
        float* Ssl = cb + 2304;
        float* kss = cb + 3456;
#pragma unroll
        for (int ks = 0; ks < 2; ks++) {
            const int kb = ks * 8;
            uint32_t qh[2][4], ql[2][4];
#pragma unroll
            for (int mt = 0; mt < 2; mt++) {
                int rb = wm * 32 + mt * 16;
                split2(Qsl[(kb + tig)     * 72 + rb + gid],     qh[mt][0], ql[mt][0]);
                split2(Qsl[(kb + tig)     * 72 + rb + gid + 8], qh[mt][1], ql[mt][1]);
                split2(Qsl[(kb + tig + 4) * 72 + rb + gid],     qh[mt][2], ql[mt][2]);
                split2(Qsl[(kb + tig + 4) * 72 + rb + gid + 8], qh[mt][3], ql[mt][3]);
            }
            uint32_t kh[2][2], kl[2][2], sh[2][2], sl_[2][2];
#pragma unroll
            for (int nt = 0; nt < 2; nt++) {
                int cbn = wn * 16 + nt * 8;
                split2(Ksl[(kb + tig)     * 72 + cbn + gid], kh[nt][0], kl[nt][0]);
                split2(Ksl[(kb + tig + 4) * 72 + cbn + gid], kh[nt][1], kl[nt][1]);
                split2(Ssl[(kb + tig)     * 72 + cbn + gid], sh[nt][0], sl_[nt][0]);
                split2(Ssl[(kb + tig + 4) * 72 + cbn + gid], sh[nt][1], sl_[nt][1]);
            }
#pragma unroll
            for (int mt = 0; mt < 2; mt++)
#pragma unroll
                for (int nt = 0; nt < 2; nt++) {
                    mma_tf32(aA[mt][nt], qh[mt], kh[nt]);
                    mma_tf32(aA[mt][nt], qh[mt], kl[nt]);
                    mma_tf32(aA[mt][nt], ql[mt], kh[nt]);
                    mma_tf32(aN[mt][nt], qh[mt], sh[nt]);
                    mma_tf32(aN[mt][nt], qh[mt], sl_[nt]);
                    mma_tf32(aN[mt][nt], ql[mt], sh[nt]);
                }
            if (wn == 0) {
                uint32_t bh[2], bl[2];
                split2(kss[kb + tig],     bh[0], bl[0]);
                split2(kss[kb + tig + 4], bh[1], bl[1]);
#pragma unroll
                for (int mt = 0; mt < 2; mt++) {
                    mma_tf32(aD[mt], qh[mt], bh);
                    mma_tf32(aD[mt], qh[mt], bl);
                    mma_tf32(aD[mt], ql[mt], bh);
                }
            }
        }
        if (s + 1 < 18) {
            float* nb = bufs + ((s + 1) & 1) * SLICE_SZ;
            *(float4*)&nb[sr * 72 + sc4]        = pq;
            *(float4*)&nb[1152 + sr * 72 + sc4] = pk;
            *(float4*)&nb[2304 + sr * 72 + sc4] = ps;
            if (tid < 16) nb[3456 + tid] = pks;
        }
        __syncthreads();
    }

    // mask scores (keep j <= i) and stash to smem
#pragma unroll
    for (int mt = 0; mt < 2; mt++)
#pragma unroll
        for (int nt = 0; nt < 2; nt++) {
            int ri0 = wm * 32 + mt * 16 + gid;
            int ri1 = ri0 + 8;
            int cb0 = wn * 16 + nt * 8 + tig * 2;
            float2 r0, r1;
            r0.x = (cb0     <= ri0) ? aA[mt][nt][0] : 0.f;
            r0.y = (cb0 + 1 <= ri0) ? aA[mt][nt][1] : 0.f;
            r1.x = (cb0     <= ri1) ? aA[mt][nt][2] : 0.f;
            r1.y = (cb0 + 1 <= ri1) ? aA[mt][nt][3] : 0.f;
            *(float2*)&Asm[ri0 * 72 + cb0] = r0;
            *(float2*)&Asm[ri1 * 72 + cb0] = r1;
        }
    __syncthreads();

    // phase 2: num += A @ V ; den += rowsum(A)
#pragma unroll
    for (int ks = 0; ks < 8; ks++) {
        const int kb = ks * 8;
        uint32_t ah[2][4], al[2][4];
#pragma unroll
        for (int mt = 0; mt < 2; mt++) {
            int rb = wm * 32 + mt * 16;
            split2(Asm[(rb + gid)     * 72 + kb + tig],     ah[mt][0], al[mt][0]);
            split2(Asm[(rb + gid + 8) * 72 + kb + tig],     ah[mt][1], al[mt][1]);
            split2(Asm[(rb + gid)     * 72 + kb + tig + 4], ah[mt][2], al[mt][2]);
            split2(Asm[(rb + gid + 8) * 72 + kb + tig + 4], ah[mt][3], al[mt][3]);
        }
#pragma unroll
        for (int nt = 0; nt < 2; nt++) {
            int cbn = wn * 16 + nt * 8;
            uint32_t bh[2], bl[2];
            split2(Vs[(kb + tig)     * 72 + cbn + gid], bh[0], bl[0]);
            split2(Vs[(kb + tig + 4) * 72 + cbn + gid], bh[1], bl[1]);
#pragma unroll
            for (int mt = 0; mt < 2; mt++) {
                mma_tf32(aN[mt][nt], ah[mt], bh);
                mma_tf32(aN[mt][nt], ah[mt], bl);
                mma_tf32(aN[mt][nt], al[mt], bh);
            }
        }
        if (wn == 0) {
#pragma unroll
            for (int mt = 0; mt < 2; mt++) {
                mma_tf32(aD[mt], ah[mt], ones);
                mma_tf32(aD[mt], al[mt], ones);
            }
        }
    }
    if (wn == 0 && tig == 0) {
#pragma unroll
        for (int mt = 0; mt < 2; mt++) {
            den[wm * 32 + mt * 16 + gid]     = aD[mt][0];
            den[wm * 32 + mt * 16 + gid + 8] = aD[mt][2];
        }
    }
    __syncthreads();

    // divide & store
#pragma unroll
    for (int mt = 0; mt < 2; mt++) {
        int ri0 = wm * 32 + mt * 16 + gid;
        int ri1 = ri0 + 8;
        float inv0 = 1.0f / (den[ri0] + 1e-12f);
        float inv1 = 1.0f / (den[ri1] + 1e-12f);
#pragma unroll
        for (int nt = 0; nt < 2; nt++) {
            int cb0 = wn * 16 + nt * 8 + tig * 2;
            *(float2*)&g_Y[(c * CH + ri0) * DM + h * HD + cb0] =
                make_float2(aN[mt][nt][0] * inv0, aN[mt][nt][1] * inv0);
            *(float2*)&g_Y[(c * CH + ri1) * DM + h * HD + cb0] =
                make_float2(aN[mt][nt][2] * inv1, aN[mt][nt][3] * inv1);
        }
    }
}

// ---------------------------------------------------------------------------
extern "C" void kernel_launch(void* const* d_in, const int* in_sizes, int n_in,
                              void* d_out, int out_size) {
    const float* hs = (const float*)d_in[0];
    const float* Wq = (const float*)d_in[1];
    const float* Wk = (const float*)d_in[2];
    const float* Wv = (const float*)d_in[3];
    const float* Wo = (const float*)d_in[4];
    float* out = (float*)d_out;

    cudaFuncSetAttribute(chunk_attn_k, cudaFuncAttributeMaxDynamicSharedMemorySize, ATTN_SMEM);
    cudaFuncSetAttribute(chunk_kv_k,   cudaFuncAttributeMaxDynamicSharedMemorySize, KV_SMEM);
    cudaFuncSetAttribute(qkv_gemm, cudaFuncAttributeMaxDynamicSharedMemorySize, SMEM_GEMM_BYTES);
    cudaFuncSetAttribute(o_gemm,   cudaFuncAttributeMaxDynamicSharedMemorySize, SMEM_GEMM_BYTES);

    dim3 thr(256);
    qkv_gemm<<<dim3(18, 8), thr, SMEM_GEMM_BYTES>>>(hs, Wq, Wk, Wv);
    featurize_k<<<dim3(NC, NH, 2), thr>>>();
    chunk_kv_k<<<dim3(2, NC, NH), 288, KV_SMEM>>>();
    {
        int total = NH * CHUNK_ELT + NH * DP;
        prefix_k<<<(total + 255) / 256, 256>>>();
    }
    chunk_attn_k<<<dim3(NC, NH), thr, ATTN_SMEM>>>();
    o_gemm<<<dim3(12, 8), thr, SMEM_GEMM_BYTES>>>(Wo, out);
}

// round 8
// speedup vs baseline: 2.5237x; 1.1677x over previous
#include <cuda_runtime.h>
#include <cstdint>

// Problem constants
#define LL 1024
#define DM 768
#define NH 12
#define FD 16
#define HD 64
#define CH 64
#define NC 16
#define DP 288           // padded expanded feature dim (273 -> 288)
#define NW 144           // DP/2 packed words
#define QK_WORDS (64*NW) // 9216 words per (h,c): [row64][nw144]
#define K2_WORDS (DP*32) // 9216 words per (h,c): [n288][iw32]
#define V_WORDS  (64*32) // 2048 words per (h,c): [d64][iw32]
#define S_ELT    (64*DP) // 18432 fp32 per (h,c), layout [d][n]

// Scratch (static device globals)
__device__ float    g_Q[LL*NH*FD];
__device__ float    g_K[LL*NH*FD];
__device__ float    g_V[LL*DM];
__device__ uint32_t g_Qh [NH*NC*QK_WORDS], g_Ql [NH*NC*QK_WORDS]; // Qf packed along n
__device__ uint32_t g_K1h[NH*NC*QK_WORDS], g_K1l[NH*NC*QK_WORDS]; // Kf packed along n (attn B)
__device__ uint32_t g_K2h[NH*NC*K2_WORDS], g_K2l[NH*NC*K2_WORDS]; // Kf packed along i (kv A)
__device__ uint32_t g_Vh [NH*NC*V_WORDS],  g_Vl [NH*NC*V_WORDS];  // V packed along token
__device__ float    g_S  [NH*NC*S_ELT];   // per-chunk KV sums, [d][n]
__device__ float    g_ks [NH*NC*DP];      // per-chunk k-feature sums
__device__ uint32_t g_Sh [NH*NC*QK_WORDS], g_Sl [NH*NC*QK_WORDS]; // prefix S packed: [d][nw]
__device__ uint32_t g_kh [NH*NC*NW],       g_kl [NH*NC*NW];       // prefix ksum packed
__device__ float    g_Y[LL*DM];

// ---------------------------------------------------------------------------
// bf16 split-pack helpers.  x = hi + lo with hi,lo bf16; dropped lo*lo ~2^-18.
// ---------------------------------------------------------------------------
__device__ __forceinline__ void split_pack(float x0, float x1, uint32_t& hi, uint32_t& lo) {
    uint32_t h;
    asm("cvt.rn.bf16x2.f32 %0, %1, %2;" : "=r"(h) : "f"(x1), "f"(x0));  // hi: x1->upper, x0->lower
    float h0 = __uint_as_float(h << 16);
    float h1 = __uint_as_float(h & 0xffff0000u);
    asm("cvt.rn.bf16x2.f32 %0, %1, %2;" : "=r"(lo) : "f"(x1 - h1), "f"(x0 - h0));
    hi = h;
}
__device__ __forceinline__ void mma_bf16(float c[4], const uint32_t a[4], const uint32_t b[2]) {
    asm volatile("mma.sync.aligned.m16n8k16.row.col.f32.bf16.bf16.f32 "
                 "{%0,%1,%2,%3}, {%4,%5,%6,%7}, {%8,%9}, {%0,%1,%2,%3};\n"
                 : "+f"(c[0]), "+f"(c[1]), "+f"(c[2]), "+f"(c[3])
                 : "r"(a[0]), "r"(a[1]), "r"(a[2]), "r"(a[3]),
                   "r"(b[0]), "r"(b[1]));
}
#define ONES2 0x3F803F80u   // (1.0bf16, 1.0bf16)

// ===========================================================================
// 3xBF16 projection GEMM: C[1024 x N] = A[1024 x K] @ B[K x N].
// Block 128x64, 256 thr = 8 warps (4x2), warp 32x32 = 2x4 m16n8k16 tiles.
// Packed bf16x2 smem (stride 12 words: conflict-free fragment LDS),
// double-buffered with register prefetch.  24 mma per K16 stage.
// ===========================================================================
#define GSMBUF 4608                       // words per buffer
#define SMEM_GEMM_BYTES (2 * GSMBUF * 4)  // 36864 B

__device__ __forceinline__ void bf16_body(const float* __restrict__ A,
                                          const float* __restrict__ B,
                                          float* __restrict__ C,
                                          int N, int K, int bm, int bn,
                                          uint32_t* sm) {
    const int tid  = threadIdx.x, lane = tid & 31, w = tid >> 5;
    const int wm = w >> 1, wn = w & 1;
    const int gid = lane >> 2, tig = lane & 3;
    const int ar = tid >> 1, aw0 = (tid & 1) * 4;   // A staging: row ar, words aw0..aw0+3
    const int bnn = tid & 63, bkq = tid >> 6;       // B staging: row bnn, words bkq*2..+1

    float acc[2][4][4] = {};
    const int nit = K / 16;

    float4 av0 = *(const float4*)&A[(bm + ar) * K + aw0 * 2];
    float4 av1 = *(const float4*)&A[(bm + ar) * K + aw0 * 2 + 4];
    float bv0 = B[(bkq * 4 + 0) * N + bn + bnn];
    float bv1 = B[(bkq * 4 + 1) * N + bn + bnn];
    float bv2 = B[(bkq * 4 + 2) * N + bn + bnn];
    float bv3 = B[(bkq * 4 + 3) * N + bn + bnn];

    auto cvst = [&](uint32_t* buf, float4 A0, float4 A1,
                    float b0, float b1, float b2, float b3) {
        uint32_t* Ah = buf;
        uint32_t* Al = buf + 1536;
        uint32_t* Bh = buf + 3072;
        uint32_t* Bl = buf + 3840;
        uint32_t h, l;
        split_pack(A0.x, A0.y, h, l); Ah[ar*12 + aw0 + 0] = h; Al[ar*12 + aw0 + 0] = l;
        split_pack(A0.z, A0.w, h, l); Ah[ar*12 + aw0 + 1] = h; Al[ar*12 + aw0 + 1] = l;
        split_pack(A1.x, A1.y, h, l); Ah[ar*12 + aw0 + 2] = h; Al[ar*12 + aw0 + 2] = l;
        split_pack(A1.z, A1.w, h, l); Ah[ar*12 + aw0 + 3] = h; Al[ar*12 + aw0 + 3] = l;
        split_pack(b0, b1, h, l);     Bh[bnn*12 + bkq*2]   = h; Bl[bnn*12 + bkq*2]   = l;
        split_pack(b2, b3, h, l);     Bh[bnn*12 + bkq*2+1] = h; Bl[bnn*12 + bkq*2+1] = l;
    };

    cvst(sm, av0, av1, bv0, bv1, bv2, bv3);
    __syncthreads();

    for (int it = 0; it < nit; it++) {
        uint32_t* cb = sm + (it & 1) * GSMBUF;
        if (it + 1 < nit) {
            int k0 = (it + 1) * 16;
            av0 = *(const float4*)&A[(bm + ar) * K + k0 + aw0 * 2];
            av1 = *(const float4*)&A[(bm + ar) * K + k0 + aw0 * 2 + 4];
            bv0 = B[(k0 + bkq * 4 + 0) * N + bn + bnn];
            bv1 = B[(k0 + bkq * 4 + 1) * N + bn + bnn];
            bv2 = B[(k0 + bkq * 4 + 2) * N + bn + bnn];
            bv3 = B[(k0 + bkq * 4 + 3) * N + bn + bnn];
        }
        uint32_t* Ah = cb;
        uint32_t* Al = cb + 1536;
        uint32_t* Bh = cb + 3072;
        uint32_t* Bl = cb + 3840;
        uint32_t ah[2][4], al_[2][4], bh[4][2], bl_[4][2];
#pragma unroll
        for (int mt = 0; mt < 2; mt++) {
            int rb = wm * 32 + mt * 16;
            ah[mt][0] = Ah[(rb+gid)*12 + tig];     ah[mt][1] = Ah[(rb+gid+8)*12 + tig];
            ah[mt][2] = Ah[(rb+gid)*12 + tig+4];   ah[mt][3] = Ah[(rb+gid+8)*12 + tig+4];
            al_[mt][0] = Al[(rb+gid)*12 + tig];    al_[mt][1] = Al[(rb+gid+8)*12 + tig];
            al_[mt][2] = Al[(rb+gid)*12 + tig+4];  al_[mt][3] = Al[(rb+gid+8)*12 + tig+4];
        }
#pragma unroll
        for (int nt = 0; nt < 4; nt++) {
            int nb = wn * 32 + nt * 8;
            bh[nt][0] = Bh[(nb+gid)*12 + tig];   bh[nt][1] = Bh[(nb+gid)*12 + tig+4];
            bl_[nt][0] = Bl[(nb+gid)*12 + tig];  bl_[nt][1] = Bl[(nb+gid)*12 + tig+4];
        }
#pragma unroll
        for (int mt = 0; mt < 2; mt++)
#pragma unroll
            for (int nt = 0; nt < 4; nt++) {
                mma_bf16(acc[mt][nt], ah[mt],  bh[nt]);
                mma_bf16(acc[mt][nt], ah[mt],  bl_[nt]);
                mma_bf16(acc[mt][nt], al_[mt], bh[nt]);
            }
        if (it + 1 < nit) cvst(sm + ((it + 1) & 1) * GSMBUF, av0, av1, bv0, bv1, bv2, bv3);
        __syncthreads();
    }

#pragma unroll
    for (int mt = 0; mt < 2; mt++)
#pragma unroll
        for (int nt = 0; nt < 4; nt++) {
            int row = bm + wm * 32 + mt * 16 + gid;
            int col = bn + wn * 32 + nt * 8 + tig * 2;
            *(float2*)&C[row * N + col]       = make_float2(acc[mt][nt][0], acc[mt][nt][1]);
            *(float2*)&C[(row + 8) * N + col] = make_float2(acc[mt][nt][2], acc[mt][nt][3]);
        }
}

__global__ __launch_bounds__(256) void qkv_gemm(const float* __restrict__ hs,
                                                const float* __restrict__ Wq,
                                                const float* __restrict__ Wk,
                                                const float* __restrict__ Wv) {
    extern __shared__ uint32_t smext[];
    const int bx = blockIdx.x, bm = blockIdx.y * 128;
    const float* B; float* C; int N, bn;
    if (bx < 3)      { B = Wq; C = g_Q; N = NH * FD; bn = bx * 64; }
    else if (bx < 6) { B = Wk; C = g_K; N = NH * FD; bn = (bx - 3) * 64; }
    else             { B = Wv; C = g_V; N = DM;      bn = (bx - 6) * 64; }
    bf16_body(hs, B, C, N, DM, bm, bn, smext);
}

__global__ __launch_bounds__(256) void o_gemm(const float* __restrict__ Wo,
                                              float* __restrict__ out) {
    extern __shared__ uint32_t smext[];
    bf16_body(g_Y, Wo, out, DM, DM, blockIdx.y * 128, blockIdx.x * 64, smext);
}

// ===========================================================================
// Featurize + pack.  grid (NC, NH, 4):
//   z=0: Q  -> g_Qh/l  [i][nw]     z=1: K -> g_K1h/l [j][nw]
//   z=2: K  -> g_K2h/l [n][iw]     z=3: V -> g_Vh/l  [d][iw]
// ===========================================================================
__global__ __launch_bounds__(256) void featurize_k() {
    const int c = blockIdx.x, h = blockIdx.y, job = blockIdx.z;
    const int tid = threadIdx.x;

    if (job == 3) {   // V transpose + pack
        // stride 68 floats = 272 B = 17*16: every row float4-aligned (65 was the
        // round-7 misaligned-address bug), 68 mod 32 = 4 keeps reads 4-way max.
        __shared__ float vs[64][68];
#pragma unroll
        for (int l = 0; l < 4; l++) {
            int fi = tid + l * 256;
            int i = fi >> 4, d4 = (fi & 15) * 4;
            *(float4*)&vs[i][d4] = *(const float4*)&g_V[(c * CH + i) * DM + h * HD + d4];
        }
        __syncthreads();
        int vb = (h * NC + c) * V_WORDS;
#pragma unroll
        for (int l = 0; l < 8; l++) {
            int wd = tid + l * 256;
            int d = wd >> 5, iw = wd & 31;
            uint32_t hi, lo;
            split_pack(vs[2 * iw][d], vs[2 * iw + 1][d], hi, lo);
            g_Vh[vb + wd] = hi; g_Vl[vb + wd] = lo;
        }
        return;
    }

    __shared__ float xs[64][17];
    const float* __restrict__ src = (job == 0) ? g_Q : g_K;
    for (int idx = tid; idx < CH * FD; idx += 256) {
        int i = idx >> 4, f = idx & 15;
        xs[i][f] = src[(c * CH + i) * (NH * FD) + h * FD + f];
    }
    __syncthreads();
    const float S1 = 0.5f;
    const float S2 = 0.17677669529663687f;
    auto feat = [&](int i, int n) -> float {
        if (n == 0)  return 1.0f;
        if (n <= 16) return xs[i][n - 1] * S1;
        if (n <= 272) { int p = n - 17; return xs[i][p >> 4] * xs[i][p & 15] * S2; }
        return 0.0f;
    };
    const int base = (h * NC + c) * QK_WORDS;
    if (job <= 1) {      // [row i][nw] packed along features
        uint32_t* dh = job ? g_K1h : g_Qh;
        uint32_t* dl = job ? g_K1l : g_Ql;
#pragma unroll 4
        for (int l = 0; l < 36; l++) {
            int wd = tid + l * 256;
            int i = wd / NW, nw = wd % NW;
            uint32_t hi, lo;
            split_pack(feat(i, 2 * nw), feat(i, 2 * nw + 1), hi, lo);
            dh[base + wd] = hi; dl[base + wd] = lo;
        }
    } else {             // job==2: [n][iw] packed along tokens
#pragma unroll 4
        for (int l = 0; l < 36; l++) {
            int wd = tid + l * 256;
            int n = wd >> 5, iw = wd & 31;
            uint32_t hi, lo;
            split_pack(feat(2 * iw, n), feat(2 * iw + 1, n), hi, lo);
            g_K2h[base + wd] = hi; g_K2l[base + wd] = lo;
        }
    }
}

// ===========================================================================
// chunk_kv (bf16 mma, smem-free): S[d][n] = sum_i Kf[n][i]*V[i][d],
// ksum[n] via ones-B.  grid (2 halves of 144 rows, NC, NH), 288 thr (9 warps).
// ===========================================================================
__global__ __launch_bounds__(288) void chunk_kv_k() {
    const int half = blockIdx.x, c = blockIdx.y, h = blockIdx.z;
    const int tid = threadIdx.x, w = tid >> 5, lane = tid & 31;
    const int gid = lane >> 2, tig = lane & 3;
    const int rbl = half * 144 + w * 16;
    const int kb2 = (h * NC + c) * K2_WORDS;
    const int vb  = (h * NC + c) * V_WORDS;
    float acc[8][4] = {}, acck[4] = {};
    const uint32_t ones[2] = { ONES2, ONES2 };

#pragma unroll
    for (int ks = 0; ks < 4; ks++) {
        const int kw = ks * 8;
        uint32_t ah[4], al_[4];
        ah[0]  = g_K2h[kb2 + (rbl+gid)*32   + kw + tig];
        ah[1]  = g_K2h[kb2 + (rbl+gid+8)*32 + kw + tig];
        ah[2]  = g_K2h[kb2 + (rbl+gid)*32   + kw + tig + 4];
        ah[3]  = g_K2h[kb2 + (rbl+gid+8)*32 + kw + tig + 4];
        al_[0] = g_K2l[kb2 + (rbl+gid)*32   + kw + tig];
        al_[1] = g_K2l[kb2 + (rbl+gid+8)*32 + kw + tig];
        al_[2] = g_K2l[kb2 + (rbl+gid)*32   + kw + tig + 4];
        al_[3] = g_K2l[kb2 + (rbl+gid+8)*32 + kw + tig + 4];
#pragma unroll
        for (int nt = 0; nt < 8; nt++) {
            uint32_t bh[2], bl_[2];
            bh[0]  = g_Vh[vb + (nt*8+gid)*32 + kw + tig];
            bh[1]  = g_Vh[vb + (nt*8+gid)*32 + kw + tig + 4];
            bl_[0] = g_Vl[vb + (nt*8+gid)*32 + kw + tig];
            bl_[1] = g_Vl[vb + (nt*8+gid)*32 + kw + tig + 4];
            mma_bf16(acc[nt], ah,  bh);
            mma_bf16(acc[nt], ah,  bl_);
            mma_bf16(acc[nt], al_, bh);
        }
        mma_bf16(acck, ah,  ones);
        mma_bf16(acck, al_, ones);
    }

    const int sb = (h * NC + c) * S_ELT;
    const int n0 = rbl + gid, n1 = n0 + 8;
#pragma unroll
    for (int nt = 0; nt < 8; nt++) {
        int d0 = nt * 8 + tig * 2;
        g_S[sb + d0 * DP + n0]       = acc[nt][0];
        g_S[sb + (d0 + 1) * DP + n0] = acc[nt][1];
        g_S[sb + d0 * DP + n1]       = acc[nt][2];
        g_S[sb + (d0 + 1) * DP + n1] = acc[nt][3];
    }
    if (tig == 0) {
        g_ks[(h * NC + c) * DP + n0] = acck[0];
        g_ks[(h * NC + c) * DP + n1] = acck[2];
    }
}

// ===========================================================================
// Exclusive prefix over chunks + bf16 pack.
// S chains: NH*64*144 threads; ksum chains: NH*144 threads.
// ===========================================================================
__global__ __launch_bounds__(256) void prefix_k() {
    const int gid = blockIdx.x * 256 + threadIdx.x;
    const int NSEG = NH * 64 * NW;   // 110592
    if (gid < NSEG) {
        int h = gid / (64 * NW), rem = gid % (64 * NW);
        int d = rem / NW, nw = rem % NW;
        const float* src = g_S + h * NC * S_ELT + d * DP + 2 * nw;
        uint32_t* dh = g_Sh + h * NC * QK_WORDS + d * NW + nw;
        uint32_t* dl = g_Sl + h * NC * QK_WORDS + d * NW + nw;
        float a0 = 0.f, a1 = 0.f;
#pragma unroll
        for (int c = 0; c < NC; c++) {
            uint32_t hi, lo;
            split_pack(a0, a1, hi, lo);
            dh[c * QK_WORDS] = hi; dl[c * QK_WORDS] = lo;
            float2 v = *(const float2*)&src[c * S_ELT];
            a0 += v.x; a1 += v.y;
        }
    } else if (gid < NSEG + NH * NW) {
        int j = gid - NSEG;
        int h = j / NW, nw = j % NW;
        const float* src = g_ks + h * NC * DP + 2 * nw;
        uint32_t* dh = g_kh + h * NC * NW + nw;
        uint32_t* dl = g_kl + h * NC * NW + nw;
        float a0 = 0.f, a1 = 0.f;
#pragma unroll
        for (int c = 0; c < NC; c++) {
            uint32_t hi, lo;
            split_pack(a0, a1, hi, lo);
            dh[c * NW] = hi; dl[c * NW] = lo;
            a0 += src[c * DP];
            a1 += src[c * DP + 1];
        }
    }
}

// ===========================================================================
// chunk_attn (bf16): per (c,h) block, 256 thr, 8 warps (wm 2 x wn 4).
// Mainloop 18 k16 stages: A += Q K^T, num += Q Sprev, den += Q ksum.
// Mask+pack scores -> smem, phase2: num += A@V, den += rowsum(A).
// All operands pre-packed bf16 hi/lo words; zero CVT in mainloop.
// ===========================================================================
#define ATTN_BUF 4624   // words: Qh 768 Ql 768 Kh 768 Kl 768 Sh 768 Sl 768 ksh 8 ksl 8
#define ATTN_SMEM ((2 * ATTN_BUF + 2 * 2304 + 64) * 4)   // 55680 B
__global__ __launch_bounds__(256, 2) void chunk_attn_k() {
    extern __shared__ uint32_t usm[];
    uint32_t* bufs = usm;                    // 2 x ATTN_BUF
    uint32_t* Ash  = usm + 2 * ATTN_BUF;     // [i][jw] stride 36
    uint32_t* Asl  = Ash + 2304;
    float*    den  = (float*)(Asl + 2304);   // [64]

    const int c = blockIdx.x, h = blockIdx.y;
    const int tid = threadIdx.x, w = tid >> 5, lane = tid & 31;
    const int wm = w >> 2, wn = w & 3;
    const int gid = lane >> 2, tig = lane & 3;

    const int qb  = (h * NC + c) * QK_WORDS;
    const int ksb = (h * NC + c) * NW;
    const int vb  = (h * NC + c) * V_WORDS;

    const uint32_t* gsrc[6] = { g_Qh + qb, g_Ql + qb, g_K1h + qb,
                                g_K1l + qb, g_Sh + qb, g_Sl + qb };
    const int sr = tid >> 3, skw = tid & 7;     // staging coords (512-word block)

    // stage slice 0
    {
#pragma unroll
        for (int o = 0; o < 6; o++)
#pragma unroll
            for (int hf = 0; hf < 2; hf++) {
                int r = sr + hf * 32;
                bufs[o * 768 + r * 12 + skw] = gsrc[o][r * NW + skw];
            }
        if (tid < 8)       bufs[4608 + tid]     = g_kh[ksb + tid];
        else if (tid < 16) bufs[4616 + tid - 8] = g_kl[ksb + tid - 8];
    }
    __syncthreads();

    float aA[2][2][4] = {}, aN[2][2][4] = {}, aD[2][4] = {};
    const uint32_t ones[2] = { ONES2, ONES2 };

    for (int s = 0; s < 18; s++) {
        uint32_t* cb = bufs + (s & 1) * ATTN_BUF;
        uint32_t pf[12]; uint32_t pks = 0;
        if (s + 1 < 18) {
            const int kw0 = (s + 1) * 8;
#pragma unroll
            for (int o = 0; o < 6; o++)
#pragma unroll
                for (int hf = 0; hf < 2; hf++) {
                    int r = sr + hf * 32;
                    pf[o * 2 + hf] = gsrc[o][r * NW + kw0 + skw];
                }
            if (tid < 8)       pks = g_kh[ksb + kw0 + tid];
            else if (tid < 16) pks = g_kl[ksb + kw0 + tid - 8];
        }
        // fragments
        uint32_t qh[2][4], ql[2][4];
#pragma unroll
        for (int mt = 0; mt < 2; mt++) {
            int rb = wm * 32 + mt * 16;
            qh[mt][0] = cb[(rb+gid)*12 + tig];         qh[mt][1] = cb[(rb+gid+8)*12 + tig];
            qh[mt][2] = cb[(rb+gid)*12 + tig+4];       qh[mt][3] = cb[(rb+gid+8)*12 + tig+4];
            ql[mt][0] = cb[768 + (rb+gid)*12 + tig];   ql[mt][1] = cb[768 + (rb+gid+8)*12 + tig];
            ql[mt][2] = cb[768 + (rb+gid)*12 + tig+4]; ql[mt][3] = cb[768 + (rb+gid+8)*12 + tig+4];
        }
        uint32_t kh[2][2], kl_[2][2], sh[2][2], sl_[2][2];
#pragma unroll
        for (int nt = 0; nt < 2; nt++) {
            int cbn = wn * 16 + nt * 8;
            kh[nt][0]  = cb[1536 + (cbn+gid)*12 + tig]; kh[nt][1]  = cb[1536 + (cbn+gid)*12 + tig+4];
            kl_[nt][0] = cb[2304 + (cbn+gid)*12 + tig]; kl_[nt][1] = cb[2304 + (cbn+gid)*12 + tig+4];
            sh[nt][0]  = cb[3072 + (cbn+gid)*12 + tig]; sh[nt][1]  = cb[3072 + (cbn+gid)*12 + tig+4];
            sl_[nt][0] = cb[3840 + (cbn+gid)*12 + tig]; sl_[nt][1] = cb[3840 + (cbn+gid)*12 + tig+4];
        }
#pragma unroll
        for (int mt = 0; mt < 2; mt++)
#pragma unroll
            for (int nt = 0; nt < 2; nt++) {
                mma_bf16(aA[mt][nt], qh[mt], kh[nt]);
                mma_bf16(aA[mt][nt], qh[mt], kl_[nt]);
                mma_bf16(aA[mt][nt], ql[mt], kh[nt]);
                mma_bf16(aN[mt][nt], qh[mt], sh[nt]);
                mma_bf16(aN[mt][nt], qh[mt], sl_[nt]);
                mma_bf16(aN[mt][nt], ql[mt], sh[nt]);
            }
        if (wn == 0) {
            uint32_t bh2[2] = { cb[4608 + tig], cb[4608 + tig + 4] };
            uint32_t bl2[2] = { cb[4616 + tig], cb[4616 + tig + 4] };
#pragma unroll
            for (int mt = 0; mt < 2; mt++) {
                mma_bf16(aD[mt], qh[mt], bh2);
                mma_bf16(aD[mt], qh[mt], bl2);
                mma_bf16(aD[mt], ql[mt], bh2);
            }
        }
        if (s + 1 < 18) {
            uint32_t* nb2 = bufs + ((s + 1) & 1) * ATTN_BUF;
#pragma unroll
            for (int o = 0; o < 6; o++)
#pragma unroll
                for (int hf = 0; hf < 2; hf++) {
                    int r = sr + hf * 32;
                    nb2[o * 768 + r * 12 + skw] = pf[o * 2 + hf];
                }
            if (tid < 8)       nb2[4608 + tid]     = pks;
            else if (tid < 16) nb2[4616 + tid - 8] = pks;
        }
        __syncthreads();
    }

    // mask scores (keep j <= i), pack, stash to smem
#pragma unroll
    for (int mt = 0; mt < 2; mt++)
#pragma unroll
        for (int nt = 0; nt < 2; nt++) {
            int ri0 = wm * 32 + mt * 16 + gid, ri1 = ri0 + 8;
            int j0 = wn * 16 + nt * 8 + tig * 2;
            int jw = wn * 8 + nt * 4 + tig;
            float x0 = (j0     <= ri0) ? aA[mt][nt][0] : 0.f;
            float x1 = (j0 + 1 <= ri0) ? aA[mt][nt][1] : 0.f;
            float x2 = (j0     <= ri1) ? aA[mt][nt][2] : 0.f;
            float x3 = (j0 + 1 <= ri1) ? aA[mt][nt][3] : 0.f;
            uint32_t hi, lo;
            split_pack(x0, x1, hi, lo); Ash[ri0 * 36 + jw] = hi; Asl[ri0 * 36 + jw] = lo;
            split_pack(x2, x3, hi, lo); Ash[ri1 * 36 + jw] = hi; Asl[ri1 * 36 + jw] = lo;
        }
    __syncthreads();

    // phase 2: num += A @ V ; den += rowsum(A)
#pragma unroll
    for (int ks = 0; ks < 4; ks++) {
        const int kw = ks * 8;
        uint32_t ah[2][4], al2[2][4];
#pragma unroll
        for (int mt = 0; mt < 2; mt++) {
            int rb = wm * 32 + mt * 16;
            ah[mt][0]  = Ash[(rb+gid)*36 + kw + tig];   ah[mt][1]  = Ash[(rb+gid+8)*36 + kw + tig];
            ah[mt][2]  = Ash[(rb+gid)*36 + kw + tig+4]; ah[mt][3]  = Ash[(rb+gid+8)*36 + kw + tig+4];
            al2[mt][0] = Asl[(rb+gid)*36 + kw + tig];   al2[mt][1] = Asl[(rb+gid+8)*36 + kw + tig];
            al2[mt][2] = Asl[(rb+gid)*36 + kw + tig+4]; al2[mt][3] = Asl[(rb+gid+8)*36 + kw + tig+4];
        }
#pragma unroll
        for (int nt = 0; nt < 2; nt++) {
            int d = wn * 16 + nt * 8 + gid;
            uint32_t bh2[2] = { g_Vh[vb + d*32 + kw + tig], g_Vh[vb + d*32 + kw + tig + 4] };
            uint32_t bl2[2] = { g_Vl[vb + d*32 + kw + tig], g_Vl[vb + d*32 + kw + tig + 4] };
#pragma unroll
            for (int mt = 0; mt < 2; mt++) {
                mma_bf16(aN[mt][nt], ah[mt],  bh2);
                mma_bf16(aN[mt][nt], ah[mt],  bl2);
                mma_bf16(aN[mt][nt], al2[mt], bh2);
            }
        }
        if (wn == 0) {
#pragma unroll
            for (int mt = 0; mt < 2; mt++) {
                mma_bf16(aD[mt], ah[mt],  ones);
                mma_bf16(aD[mt], al2[mt], ones);
            }
        }
    }
    if (wn == 0 && tig == 0) {
#pragma unroll
        for (int mt = 0; mt < 2; mt++) {
            den[wm * 32 + mt * 16 + gid]     = aD[mt][0];
            den[wm * 32 + mt * 16 + gid + 8] = aD[mt][2];
        }
    }
    __syncthreads();

    // divide & store
#pragma unroll
    for (int mt = 0; mt < 2; mt++) {
        int ri0 = wm * 32 + mt * 16 + gid, ri1 = ri0 + 8;
        float inv0 = 1.0f / (den[ri0] + 1e-12f);
        float inv1 = 1.0f / (den[ri1] + 1e-12f);
#pragma unroll
        for (int nt = 0; nt < 2; nt++) {
            int cb0 = wn * 16 + nt * 8 + tig * 2;
            *(float2*)&g_Y[(c * CH + ri0) * DM + h * HD + cb0] =
                make_float2(aN[mt][nt][0] * inv0, aN[mt][nt][1] * inv0);
            *(float2*)&g_Y[(c * CH + ri1) * DM + h * HD + cb0] =
                make_float2(aN[mt][nt][2] * inv1, aN[mt][nt][3] * inv1);
        }
    }
}

// ---------------------------------------------------------------------------
extern "C" void kernel_launch(void* const* d_in, const int* in_sizes, int n_in,
                              void* d_out, int out_size) {
    const float* hs = (const float*)d_in[0];
    const float* Wq = (const float*)d_in[1];
    const float* Wk = (const float*)d_in[2];
    const float* Wv = (const float*)d_in[3];
    const float* Wo = (const float*)d_in[4];
    float* out = (float*)d_out;

    cudaFuncSetAttribute(chunk_attn_k, cudaFuncAttributeMaxDynamicSharedMemorySize, ATTN_SMEM);
    cudaFuncSetAttribute(qkv_gemm, cudaFuncAttributeMaxDynamicSharedMemorySize, SMEM_GEMM_BYTES);
    cudaFuncSetAttribute(o_gemm,   cudaFuncAttributeMaxDynamicSharedMemorySize, SMEM_GEMM_BYTES);

    dim3 thr(256);
    qkv_gemm<<<dim3(18, 8), thr, SMEM_GEMM_BYTES>>>(hs, Wq, Wk, Wv);
    featurize_k<<<dim3(NC, NH, 4), thr>>>();
    chunk_kv_k<<<dim3(2, NC, NH), 288>>>();
    {
        int total = NH * 64 * NW + NH * NW;   // 112320
        prefix_k<<<(total + 255) / 256, 256>>>();
    }
    chunk_attn_k<<<dim3(NC, NH), thr, ATTN_SMEM>>>();
    o_gemm<<<dim3(12, 8), thr, SMEM_GEMM_BYTES>>>(Wo, out);
}